// round 1
// baseline (speedup 1.0000x reference)
#include <cuda_runtime.h>
#include <math.h>

#define B_ 2
#define T_ 2048
#define C_ 1024
#define H_ 16
#define D_ 64
#define M_ (B_*T_)          // 4096
#define NQKV (3*C_)         // 3072

// Scratch (allocation-free rule: __device__ globals)
__device__ float g_q[(size_t)B_*H_*T_*D_];
__device__ float g_k[(size_t)B_*H_*T_*D_];
__device__ float g_v[(size_t)B_*H_*T_*D_];
__device__ float g_att[(size_t)M_*C_];   // [b][t][h][d] == [M, C] row-major

// ---------------------------------------------------------------------------
// SGEMM 128x128x8, 256 threads, 8x8 per thread.
// ---------------------------------------------------------------------------
__global__ __launch_bounds__(256) void qkv_gemm(const float* __restrict__ A,
                                                const float* __restrict__ Bw) {
    const int K = C_, N = NQKV;
    __shared__ float As[8][128];
    __shared__ float Bs[8][128];
    int tid = threadIdx.x;
    int tx = tid & 15, ty = tid >> 4;
    int m0 = blockIdx.y * 128;
    int n0 = blockIdx.x * 128;

    int arow = tid >> 1, ac4 = (tid & 1) * 4;
    int brow = tid >> 5, bc4 = (tid & 31) * 4;
    const float* Ap = A + (size_t)(m0 + arow) * K + ac4;
    const float* Bp = Bw + (size_t)brow * N + n0 + bc4;

    float acc[8][8] = {};

    for (int k0 = 0; k0 < K; k0 += 8) {
        float4 av = *(const float4*)(Ap + k0);
        float4 bv = *(const float4*)(Bp + (size_t)k0 * N);
        As[ac4+0][arow] = av.x; As[ac4+1][arow] = av.y;
        As[ac4+2][arow] = av.z; As[ac4+3][arow] = av.w;
        *(float4*)&Bs[brow][bc4] = bv;
        __syncthreads();
        #pragma unroll
        for (int kk = 0; kk < 8; ++kk) {
            float a[8], b[8];
            *(float4*)(a)   = *(float4*)&As[kk][ty*8];
            *(float4*)(a+4) = *(float4*)&As[kk][ty*8+4];
            *(float4*)(b)   = *(float4*)&Bs[kk][tx*8];
            *(float4*)(b+4) = *(float4*)&Bs[kk][tx*8+4];
            #pragma unroll
            for (int i = 0; i < 8; ++i)
                #pragma unroll
                for (int j = 0; j < 8; ++j)
                    acc[i][j] += a[i] * b[j];
        }
        __syncthreads();
    }

    // Epilogue: de-interleave qkv. n = (h*64+d)*3 + three
    #pragma unroll
    for (int i = 0; i < 8; ++i) {
        int m = m0 + ty*8 + i;
        int bb = m / T_, t = m % T_;
        #pragma unroll
        for (int j = 0; j < 8; ++j) {
            int n = n0 + tx*8 + j;
            int three = n % 3;
            int hd = n / 3;
            int h = hd >> 6, d = hd & 63;
            size_t dst = (((size_t)(bb*H_ + h))*T_ + t)*D_ + d;
            float v = acc[i][j];
            if (three == 0)      g_q[dst] = v;
            else if (three == 1) g_k[dst] = v;
            else                 g_v[dst] = v;
        }
    }
}

__global__ __launch_bounds__(256) void proj_gemm(const float* __restrict__ Bw,
                                                 const float* __restrict__ bias,
                                                 float* __restrict__ out) {
    const int K = C_, N = C_;
    __shared__ float As[8][128];
    __shared__ float Bs[8][128];
    int tid = threadIdx.x;
    int tx = tid & 15, ty = tid >> 4;
    int m0 = blockIdx.y * 128;
    int n0 = blockIdx.x * 128;

    int arow = tid >> 1, ac4 = (tid & 1) * 4;
    int brow = tid >> 5, bc4 = (tid & 31) * 4;
    const float* Ap = g_att + (size_t)(m0 + arow) * K + ac4;
    const float* Bp = Bw + (size_t)brow * N + n0 + bc4;

    float acc[8][8] = {};

    for (int k0 = 0; k0 < K; k0 += 8) {
        float4 av = *(const float4*)(Ap + k0);
        float4 bv = *(const float4*)(Bp + (size_t)k0 * N);
        As[ac4+0][arow] = av.x; As[ac4+1][arow] = av.y;
        As[ac4+2][arow] = av.z; As[ac4+3][arow] = av.w;
        *(float4*)&Bs[brow][bc4] = bv;
        __syncthreads();
        #pragma unroll
        for (int kk = 0; kk < 8; ++kk) {
            float a[8], b[8];
            *(float4*)(a)   = *(float4*)&As[kk][ty*8];
            *(float4*)(a+4) = *(float4*)&As[kk][ty*8+4];
            *(float4*)(b)   = *(float4*)&Bs[kk][tx*8];
            *(float4*)(b+4) = *(float4*)&Bs[kk][tx*8+4];
            #pragma unroll
            for (int i = 0; i < 8; ++i)
                #pragma unroll
                for (int j = 0; j < 8; ++j)
                    acc[i][j] += a[i] * b[j];
        }
        __syncthreads();
    }

    #pragma unroll
    for (int i = 0; i < 8; ++i) {
        int m = m0 + ty*8 + i;
        #pragma unroll
        for (int j = 0; j < 8; ++j) {
            int n = n0 + tx*8 + j;
            out[(size_t)m * N + n] = acc[i][j] + bias[n];
        }
    }
}

// ---------------------------------------------------------------------------
// Flash attention, fp32. BQ=64 queries/block, BK=64 keys/tile, 256 threads.
// Qt/Kt stored d-major (transposed) so phase-A fragment loads are float4.
// KP buffer is reused: K^T during phase A, P^T (probs transposed) for phase C.
// ---------------------------------------------------------------------------
#define PAD 68   // 64 + 4: float4-aligned, conflict-free column writes

__global__ __launch_bounds__(256) void attn_kernel() {
    extern __shared__ float sm[];
    float* Qt   = sm;                 // [64][PAD]  Qt[d][i]
    float* KP   = Qt + 64*PAD;        // [64][PAD]  Kt[d][j] -> Pt[j][i]
    float* Vs   = KP + 64*PAD;        // [64][PAD]  Vs[k][d]
    float* Ss   = Vs + 64*PAD;        // [64][PAD]  S[i][j]
    float* mrow = Ss + 64*PAD;        // [64]
    float* lrow = mrow + 64;          // [64]
    float* rrow = lrow + 64;          // [64]

    int tid = threadIdx.x;
    int tx = tid & 15, ty = tid >> 4;
    int bh = blockIdx.y;
    int b = bh >> 4, h = bh & 15;
    int qBase = blockIdx.x * 64;

    const float* qg  = g_q + (((size_t)(b*H_ + h))*T_ + qBase)*D_;
    const float* kgb = g_k + ((size_t)(b*H_ + h))*T_*D_;
    const float* vgb = g_v + ((size_t)(b*H_ + h))*T_*D_;

    // Load Q transposed into smem
    {
        int i = tid & 63, dg = tid >> 6;
        #pragma unroll
        for (int it = 0; it < 4; ++it) {
            int d4 = (dg + it*4) * 4;
            float4 v = *(const float4*)(qg + (size_t)i*D_ + d4);
            Qt[(d4+0)*PAD + i] = v.x;
            Qt[(d4+1)*PAD + i] = v.y;
            Qt[(d4+2)*PAD + i] = v.z;
            Qt[(d4+3)*PAD + i] = v.w;
        }
    }
    if (tid < 64) { mrow[tid] = -INFINITY; lrow[tid] = 0.0f; }

    float o[4][4] = {};
    const float scale = 0.125f;   // D^-0.5
    int nkt = blockIdx.x + 1;     // causal: only tiles kBase <= qBase

    for (int kt = 0; kt < nkt; ++kt) {
        int kBase = kt * 64;
        __syncthreads();   // prior tile's readers done; Qt load visible (1st iter)

        // Load K transposed, V natural
        {
            const float* kg = kgb + (size_t)kBase * D_;
            int i = tid & 63, dg = tid >> 6;
            #pragma unroll
            for (int it = 0; it < 4; ++it) {
                int d4 = (dg + it*4) * 4;
                float4 v = *(const float4*)(kg + (size_t)i*D_ + d4);
                KP[(d4+0)*PAD + i] = v.x;
                KP[(d4+1)*PAD + i] = v.y;
                KP[(d4+2)*PAD + i] = v.z;
                KP[(d4+3)*PAD + i] = v.w;
            }
            const float* vg = vgb + (size_t)kBase * D_;
            #pragma unroll
            for (int it = 0; it < 4; ++it) {
                int idx = tid + it*256;
                int kk = idx >> 4, d4 = (idx & 15) * 4;
                *(float4*)&Vs[kk*PAD + d4] = *(const float4*)(vg + (size_t)kk*D_ + d4);
            }
        }
        __syncthreads();

        // Phase A: S = Q K^T  (4x4 per thread)
        {
            float c4[4][4] = {};
            #pragma unroll 16
            for (int d = 0; d < 64; ++d) {
                float4 a  = *(float4*)&Qt[d*PAD + ty*4];
                float4 bk = *(float4*)&KP[d*PAD + tx*4];
                float af[4] = {a.x, a.y, a.z, a.w};
                float bf[4] = {bk.x, bk.y, bk.z, bk.w};
                #pragma unroll
                for (int i = 0; i < 4; ++i)
                    #pragma unroll
                    for (int j = 0; j < 4; ++j)
                        c4[i][j] += af[i] * bf[j];
            }
            #pragma unroll
            for (int i = 0; i < 4; ++i) {
                int qi = qBase + ty*4 + i;
                #pragma unroll
                for (int j = 0; j < 4; ++j) {
                    int kj = kBase + tx*4 + j;
                    Ss[(ty*4+i)*PAD + tx*4+j] = (kj <= qi) ? c4[i][j]*scale : -INFINITY;
                }
            }
        }
        __syncthreads();

        // Phase B: online softmax; write P transposed into KP
        {
            int row = tid >> 2, g = tid & 3;
            float sv[16];
            float lm = -INFINITY;
            #pragma unroll
            for (int j = 0; j < 16; ++j) {
                sv[j] = Ss[row*PAD + g*16 + j];
                lm = fmaxf(lm, sv[j]);
            }
            lm = fmaxf(lm, __shfl_xor_sync(0xffffffffu, lm, 1));
            lm = fmaxf(lm, __shfl_xor_sync(0xffffffffu, lm, 2));
            float newm = fmaxf(mrow[row], lm);
            float ls = 0.0f;
            #pragma unroll
            for (int j = 0; j < 16; ++j) {
                float p = __expf(sv[j] - newm);
                ls += p;
                KP[(g*16+j)*PAD + row] = p;   // Pt[key][query]
            }
            ls += __shfl_xor_sync(0xffffffffu, ls, 1);
            ls += __shfl_xor_sync(0xffffffffu, ls, 2);
            if (g == 0) {
                float r = __expf(mrow[row] - newm);
                rrow[row] = r;
                lrow[row] = lrow[row] * r + ls;
                mrow[row] = newm;
            }
        }
        __syncthreads();

        // Phase C: O = O*r + P V  (4x4 per thread)
        {
            float rr[4];
            #pragma unroll
            for (int i = 0; i < 4; ++i) rr[i] = rrow[ty*4 + i];
            #pragma unroll
            for (int i = 0; i < 4; ++i)
                #pragma unroll
                for (int j = 0; j < 4; ++j)
                    o[i][j] *= rr[i];
            #pragma unroll 16
            for (int k = 0; k < 64; ++k) {
                float4 a = *(float4*)&KP[k*PAD + ty*4];
                float4 v = *(float4*)&Vs[k*PAD + tx*4];
                float af[4] = {a.x, a.y, a.z, a.w};
                float vf[4] = {v.x, v.y, v.z, v.w};
                #pragma unroll
                for (int i = 0; i < 4; ++i)
                    #pragma unroll
                    for (int j = 0; j < 4; ++j)
                        o[i][j] += af[i] * vf[j];
            }
        }
    }

    // Epilogue: normalize, write [b][t][h][d]
    #pragma unroll
    for (int i = 0; i < 4; ++i) {
        int qi = ty*4 + i;
        float inv = 1.0f / lrow[qi];
        int t = qBase + qi;
        float* og = g_att + (((size_t)(b*T_ + t))*H_ + h)*D_ + tx*4;
        float4 w;
        w.x = o[i][0]*inv; w.y = o[i][1]*inv; w.z = o[i][2]*inv; w.w = o[i][3]*inv;
        *(float4*)og = w;
    }
}

// ---------------------------------------------------------------------------
extern "C" void kernel_launch(void* const* d_in, const int* in_sizes, int n_in,
                              void* d_out, int out_size) {
    const float* x      = (const float*)d_in[0];
    const float* w_qkv  = (const float*)d_in[1];
    const float* w_proj = (const float*)d_in[2];
    const float* b_proj = (const float*)d_in[3];
    float* out = (float*)d_out;

    const int ATTN_SMEM = (4*64*PAD + 3*64) * (int)sizeof(float);  // 70400 B
    cudaFuncSetAttribute(attn_kernel,
                         cudaFuncAttributeMaxDynamicSharedMemorySize, ATTN_SMEM);

    qkv_gemm<<<dim3(NQKV/128, M_/128), 256>>>(x, w_qkv);
    attn_kernel<<<dim3(T_/64, B_*H_), 256, ATTN_SMEM>>>();
    proj_gemm<<<dim3(C_/128, M_/128), 256>>>(w_proj, b_proj, out);
}

// round 2
// speedup vs baseline: 1.0257x; 1.0257x over previous
#include <cuda_runtime.h>
#include <math.h>

#define B_ 2
#define T_ 2048
#define C_ 1024
#define H_ 16
#define D_ 64
#define M_ (B_*T_)          // 4096
#define NQKV (3*C_)         // 3072

typedef unsigned long long u64;

// Packed f32x2 helpers (Blackwell sm_103a). mov.b64 {lo,hi} packing of
// already-adjacent registers coalesces to nothing in SASS; the duplicate-pack
// for the broadcast operand costs one MOV on the alu pipe.
__device__ __forceinline__ u64 pk2(float x, float y) {
    u64 d; asm("mov.b64 %0, {%1, %2};" : "=l"(d) : "f"(x), "f"(y)); return d;
}
__device__ __forceinline__ void upk2(u64 v, float& x, float& y) {
    asm("mov.b64 {%0, %1}, %2;" : "=f"(x), "=f"(y) : "l"(v));
}
__device__ __forceinline__ u64 ffma2(u64 a, u64 b, u64 c) {
    u64 d; asm("fma.rn.f32x2 %0, %1, %2, %3;" : "=l"(d) : "l"(a), "l"(b), "l"(c)); return d;
}
__device__ __forceinline__ u64 fmul2(u64 a, u64 b) {
    u64 d; asm("mul.rn.f32x2 %0, %1, %2;" : "=l"(d) : "l"(a), "l"(b)); return d;
}

// Scratch (allocation-free rule: __device__ globals)
__device__ float g_q[(size_t)B_*H_*T_*D_];
__device__ float g_k[(size_t)B_*H_*T_*D_];
__device__ float g_v[(size_t)B_*H_*T_*D_];
__device__ float g_att[(size_t)M_*C_];   // [b][t][h][d] == [M, C] row-major

// ---------------------------------------------------------------------------
// SGEMM 128x128x8, 256 threads, 8x8 per thread, f32x2 packed inner loop.
// ---------------------------------------------------------------------------
__global__ __launch_bounds__(256) void qkv_gemm(const float* __restrict__ A,
                                                const float* __restrict__ Bw) {
    const int K = C_, N = NQKV;
    __shared__ float As[8][128];
    __shared__ float Bs[8][128];
    int tid = threadIdx.x;
    int tx = tid & 15, ty = tid >> 4;
    int m0 = blockIdx.y * 128;
    int n0 = blockIdx.x * 128;

    int arow = tid >> 1, ac4 = (tid & 1) * 4;
    int brow = tid >> 5, bc4 = (tid & 31) * 4;
    const float* Ap = A + (size_t)(m0 + arow) * K + ac4;
    const float* Bp = Bw + (size_t)brow * N + n0 + bc4;

    u64 acc2[8][4] = {};

    for (int k0 = 0; k0 < K; k0 += 8) {
        float4 av = *(const float4*)(Ap + k0);
        float4 bv = *(const float4*)(Bp + (size_t)k0 * N);
        As[ac4+0][arow] = av.x; As[ac4+1][arow] = av.y;
        As[ac4+2][arow] = av.z; As[ac4+3][arow] = av.w;
        *(float4*)&Bs[brow][bc4] = bv;
        __syncthreads();
        #pragma unroll
        for (int kk = 0; kk < 8; ++kk) {
            float a[8], b[8];
            *(float4*)(a)   = *(float4*)&As[kk][ty*8];
            *(float4*)(a+4) = *(float4*)&As[kk][ty*8+4];
            *(float4*)(b)   = *(float4*)&Bs[kk][tx*8];
            *(float4*)(b+4) = *(float4*)&Bs[kk][tx*8+4];
            u64 b2[4] = {pk2(b[0],b[1]), pk2(b[2],b[3]),
                         pk2(b[4],b[5]), pk2(b[6],b[7])};
            #pragma unroll
            for (int i = 0; i < 8; ++i) {
                u64 aa = pk2(a[i], a[i]);
                #pragma unroll
                for (int j = 0; j < 4; ++j)
                    acc2[i][j] = ffma2(aa, b2[j], acc2[i][j]);
            }
        }
        __syncthreads();
    }

    // Epilogue: de-interleave qkv. n = (h*64+d)*3 + three
    #pragma unroll
    for (int i = 0; i < 8; ++i) {
        int m = m0 + ty*8 + i;
        int bb = m / T_, t = m % T_;
        float acc[8];
        #pragma unroll
        for (int j = 0; j < 4; ++j) upk2(acc2[i][j], acc[2*j], acc[2*j+1]);
        #pragma unroll
        for (int j = 0; j < 8; ++j) {
            int n = n0 + tx*8 + j;
            int three = n % 3;
            int hd = n / 3;
            int h = hd >> 6, d = hd & 63;
            size_t dst = (((size_t)(bb*H_ + h))*T_ + t)*D_ + d;
            float v = acc[j];
            if (three == 0)      g_q[dst] = v;
            else if (three == 1) g_k[dst] = v;
            else                 g_v[dst] = v;
        }
    }
}

__global__ __launch_bounds__(256) void proj_gemm(const float* __restrict__ Bw,
                                                 const float* __restrict__ bias,
                                                 float* __restrict__ out) {
    const int K = C_, N = C_;
    __shared__ float As[8][128];
    __shared__ float Bs[8][128];
    int tid = threadIdx.x;
    int tx = tid & 15, ty = tid >> 4;
    int m0 = blockIdx.y * 128;
    int n0 = blockIdx.x * 128;

    int arow = tid >> 1, ac4 = (tid & 1) * 4;
    int brow = tid >> 5, bc4 = (tid & 31) * 4;
    const float* Ap = g_att + (size_t)(m0 + arow) * K + ac4;
    const float* Bp = Bw + (size_t)brow * N + n0 + bc4;

    u64 acc2[8][4] = {};

    for (int k0 = 0; k0 < K; k0 += 8) {
        float4 av = *(const float4*)(Ap + k0);
        float4 bv = *(const float4*)(Bp + (size_t)k0 * N);
        As[ac4+0][arow] = av.x; As[ac4+1][arow] = av.y;
        As[ac4+2][arow] = av.z; As[ac4+3][arow] = av.w;
        *(float4*)&Bs[brow][bc4] = bv;
        __syncthreads();
        #pragma unroll
        for (int kk = 0; kk < 8; ++kk) {
            float a[8], b[8];
            *(float4*)(a)   = *(float4*)&As[kk][ty*8];
            *(float4*)(a+4) = *(float4*)&As[kk][ty*8+4];
            *(float4*)(b)   = *(float4*)&Bs[kk][tx*8];
            *(float4*)(b+4) = *(float4*)&Bs[kk][tx*8+4];
            u64 b2[4] = {pk2(b[0],b[1]), pk2(b[2],b[3]),
                         pk2(b[4],b[5]), pk2(b[6],b[7])};
            #pragma unroll
            for (int i = 0; i < 8; ++i) {
                u64 aa = pk2(a[i], a[i]);
                #pragma unroll
                for (int j = 0; j < 4; ++j)
                    acc2[i][j] = ffma2(aa, b2[j], acc2[i][j]);
            }
        }
        __syncthreads();
    }

    #pragma unroll
    for (int i = 0; i < 8; ++i) {
        int m = m0 + ty*8 + i;
        float acc[8];
        #pragma unroll
        for (int j = 0; j < 4; ++j) upk2(acc2[i][j], acc[2*j], acc[2*j+1]);
        #pragma unroll
        for (int j = 0; j < 8; ++j) {
            int n = n0 + tx*8 + j;
            out[(size_t)m * N + n] = acc[j] + bias[n];
        }
    }
}

// ---------------------------------------------------------------------------
// Flash attention, fp32 with f32x2 packed matmul phases.
// BQ=64 queries/block, BK=64 keys/tile, 256 threads.
// ---------------------------------------------------------------------------
#define PAD 68   // 64 + 4: float4-aligned, conflict-free column writes

__global__ __launch_bounds__(256) void attn_kernel() {
    extern __shared__ float sm[];
    float* Qt   = sm;                 // [64][PAD]  Qt[d][i]
    float* KP   = Qt + 64*PAD;        // [64][PAD]  Kt[d][j] -> Pt[j][i]
    float* Vs   = KP + 64*PAD;        // [64][PAD]  Vs[k][d]
    float* Ss   = Vs + 64*PAD;        // [64][PAD]  S[i][j]
    float* mrow = Ss + 64*PAD;        // [64]
    float* lrow = mrow + 64;          // [64]
    float* rrow = lrow + 64;          // [64]

    int tid = threadIdx.x;
    int tx = tid & 15, ty = tid >> 4;
    int bh = blockIdx.y;
    int b = bh >> 4, h = bh & 15;
    int qBase = blockIdx.x * 64;

    const float* qg  = g_q + (((size_t)(b*H_ + h))*T_ + qBase)*D_;
    const float* kgb = g_k + ((size_t)(b*H_ + h))*T_*D_;
    const float* vgb = g_v + ((size_t)(b*H_ + h))*T_*D_;

    // Load Q transposed into smem
    {
        int i = tid & 63, dg = tid >> 6;
        #pragma unroll
        for (int it = 0; it < 4; ++it) {
            int d4 = (dg + it*4) * 4;
            float4 v = *(const float4*)(qg + (size_t)i*D_ + d4);
            Qt[(d4+0)*PAD + i] = v.x;
            Qt[(d4+1)*PAD + i] = v.y;
            Qt[(d4+2)*PAD + i] = v.z;
            Qt[(d4+3)*PAD + i] = v.w;
        }
    }
    if (tid < 64) { mrow[tid] = -INFINITY; lrow[tid] = 0.0f; }

    u64 o2[4][2] = {};                // packed O accumulator [4 rows][4 cols as 2 pairs]
    const float scale = 0.125f;       // D^-0.5
    int nkt = blockIdx.x + 1;         // causal: only tiles kBase <= qBase

    for (int kt = 0; kt < nkt; ++kt) {
        int kBase = kt * 64;
        __syncthreads();   // prior tile's readers done; Qt load visible (1st iter)

        // Load K transposed, V natural
        {
            const float* kg = kgb + (size_t)kBase * D_;
            int i = tid & 63, dg = tid >> 6;
            #pragma unroll
            for (int it = 0; it < 4; ++it) {
                int d4 = (dg + it*4) * 4;
                float4 v = *(const float4*)(kg + (size_t)i*D_ + d4);
                KP[(d4+0)*PAD + i] = v.x;
                KP[(d4+1)*PAD + i] = v.y;
                KP[(d4+2)*PAD + i] = v.z;
                KP[(d4+3)*PAD + i] = v.w;
            }
            const float* vg = vgb + (size_t)kBase * D_;
            #pragma unroll
            for (int it = 0; it < 4; ++it) {
                int idx = tid + it*256;
                int kk = idx >> 4, d4 = (idx & 15) * 4;
                *(float4*)&Vs[kk*PAD + d4] = *(const float4*)(vg + (size_t)kk*D_ + d4);
            }
        }
        __syncthreads();

        // Phase A: S = Q K^T  (4x4 per thread, packed)
        {
            u64 c2[4][2] = {};
            #pragma unroll 8
            for (int d = 0; d < 64; ++d) {
                float4 a  = *(float4*)&Qt[d*PAD + ty*4];
                float4 bk = *(float4*)&KP[d*PAD + tx*4];
                u64 b2lo = pk2(bk.x, bk.y), b2hi = pk2(bk.z, bk.w);
                float af[4] = {a.x, a.y, a.z, a.w};
                #pragma unroll
                for (int i = 0; i < 4; ++i) {
                    u64 aa = pk2(af[i], af[i]);
                    c2[i][0] = ffma2(aa, b2lo, c2[i][0]);
                    c2[i][1] = ffma2(aa, b2hi, c2[i][1]);
                }
            }
            #pragma unroll
            for (int i = 0; i < 4; ++i) {
                float c4[4];
                upk2(c2[i][0], c4[0], c4[1]);
                upk2(c2[i][1], c4[2], c4[3]);
                int qi = qBase + ty*4 + i;
                #pragma unroll
                for (int j = 0; j < 4; ++j) {
                    int kj = kBase + tx*4 + j;
                    Ss[(ty*4+i)*PAD + tx*4+j] = (kj <= qi) ? c4[j]*scale : -INFINITY;
                }
            }
        }
        __syncthreads();

        // Phase B: online softmax; write P transposed into KP
        {
            int row = tid >> 2, g = tid & 3;
            float sv[16];
            float lm = -INFINITY;
            #pragma unroll
            for (int j = 0; j < 16; ++j) {
                sv[j] = Ss[row*PAD + g*16 + j];
                lm = fmaxf(lm, sv[j]);
            }
            lm = fmaxf(lm, __shfl_xor_sync(0xffffffffu, lm, 1));
            lm = fmaxf(lm, __shfl_xor_sync(0xffffffffu, lm, 2));
            float newm = fmaxf(mrow[row], lm);
            float ls = 0.0f;
            #pragma unroll
            for (int j = 0; j < 16; ++j) {
                float p = __expf(sv[j] - newm);
                ls += p;
                KP[(g*16+j)*PAD + row] = p;   // Pt[key][query]
            }
            ls += __shfl_xor_sync(0xffffffffu, ls, 1);
            ls += __shfl_xor_sync(0xffffffffu, ls, 2);
            if (g == 0) {
                float r = __expf(mrow[row] - newm);
                rrow[row] = r;
                lrow[row] = lrow[row] * r + ls;
                mrow[row] = newm;
            }
        }
        __syncthreads();

        // Phase C: O = O*r + P V  (4x4 per thread, packed)
        {
            #pragma unroll
            for (int i = 0; i < 4; ++i) {
                float r = rrow[ty*4 + i];
                u64 rr = pk2(r, r);
                o2[i][0] = fmul2(o2[i][0], rr);
                o2[i][1] = fmul2(o2[i][1], rr);
            }
            #pragma unroll 8
            for (int k = 0; k < 64; ++k) {
                float4 a = *(float4*)&KP[k*PAD + ty*4];
                float4 v = *(float4*)&Vs[k*PAD + tx*4];
                u64 v2lo = pk2(v.x, v.y), v2hi = pk2(v.z, v.w);
                float af[4] = {a.x, a.y, a.z, a.w};
                #pragma unroll
                for (int i = 0; i < 4; ++i) {
                    u64 aa = pk2(af[i], af[i]);
                    o2[i][0] = ffma2(aa, v2lo, o2[i][0]);
                    o2[i][1] = ffma2(aa, v2hi, o2[i][1]);
                }
            }
        }
    }

    // Epilogue: normalize, write [b][t][h][d]
    #pragma unroll
    for (int i = 0; i < 4; ++i) {
        int qi = ty*4 + i;
        float inv = 1.0f / lrow[qi];
        int t = qBase + qi;
        float* og = g_att + (((size_t)(b*T_ + t))*H_ + h)*D_ + tx*4;
        float o[4];
        upk2(o2[i][0], o[0], o[1]);
        upk2(o2[i][1], o[2], o[3]);
        float4 w;
        w.x = o[0]*inv; w.y = o[1]*inv; w.z = o[2]*inv; w.w = o[3]*inv;
        *(float4*)og = w;
    }
}

// ---------------------------------------------------------------------------
extern "C" void kernel_launch(void* const* d_in, const int* in_sizes, int n_in,
                              void* d_out, int out_size) {
    const float* x      = (const float*)d_in[0];
    const float* w_qkv  = (const float*)d_in[1];
    const float* w_proj = (const float*)d_in[2];
    const float* b_proj = (const float*)d_in[3];
    float* out = (float*)d_out;

    const int ATTN_SMEM = (4*64*PAD + 3*64) * (int)sizeof(float);  // 70400 B
    cudaFuncSetAttribute(attn_kernel,
                         cudaFuncAttributeMaxDynamicSharedMemorySize, ATTN_SMEM);

    qkv_gemm<<<dim3(NQKV/128, M_/128), 256>>>(x, w_qkv);
    attn_kernel<<<dim3(T_/64, B_*H_), 256, ATTN_SMEM>>>();
    proj_gemm<<<dim3(C_/128, M_/128), 256>>>(w_proj, b_proj, out);
}

// round 3
// speedup vs baseline: 1.6412x; 1.6002x over previous
#include <cuda_runtime.h>
#include <math.h>

#define B_ 2
#define T_ 2048
#define C_ 1024
#define H_ 16
#define D_ 64
#define M_ (B_*T_)          // 4096
#define NQKV (3*C_)         // 3072

typedef unsigned int u32;
typedef unsigned long long u64;

// Scratch (allocation-free rule: __device__ globals)
__device__ float g_q[(size_t)B_*H_*T_*D_];
__device__ float g_k[(size_t)B_*H_*T_*D_];
__device__ float g_v[(size_t)B_*H_*T_*D_];
__device__ float g_att[(size_t)M_*C_];   // [b][t][h][d] == [M, C] row-major

__device__ __forceinline__ u32 f2tf(float x) {
    u32 r; asm("cvt.rna.tf32.f32 %0, %1;" : "=r"(r) : "f"(x)); return r;
}
__device__ __forceinline__ void mma_tf32(float c[4], u32 a0, u32 a1, u32 a2, u32 a3,
                                         u32 b0, u32 b1) {
    asm volatile("mma.sync.aligned.m16n8k8.row.col.f32.tf32.tf32.f32 "
                 "{%0,%1,%2,%3}, {%4,%5,%6,%7}, {%8,%9}, {%0,%1,%2,%3};"
                 : "+f"(c[0]), "+f"(c[1]), "+f"(c[2]), "+f"(c[3])
                 : "r"(a0), "r"(a1), "r"(a2), "r"(a3), "r"(b0), "r"(b1));
}

// ---------------------------------------------------------------------------
// tf32 tensor-core GEMM: 128x128 tile, BK=32, 256 threads (8 warps, 2m x 4n,
// each warp 64x32 via 4x4 m16n8k8 tiles). A,B converted to tf32 at smem store.
// As stride 36, Bs stride 132: fragment LDS conflict-free ((4r+c)&31 distinct).
// ---------------------------------------------------------------------------
#define AS_STRIDE 36
#define BS_STRIDE 132

struct GemmFrags { float c[4][4][4]; };   // [mt][nt][frag]

template<int NDIM>
__device__ __forceinline__ void gemm_tf32_body(const float* __restrict__ A,
                                               const float* __restrict__ Bw,
                                               u32 (*As)[AS_STRIDE],
                                               u32 (*Bs)[BS_STRIDE],
                                               int m0, int n0, GemmFrags& F) {
    const int K = C_;
    int tid = threadIdx.x;
    int lane = tid & 31, wid = tid >> 5;
    int warp_m = wid >> 2, warp_n = wid & 3;    // 2 x 4
    int lr = lane >> 2, lc = lane & 3;

    for (int k0 = 0; k0 < K; k0 += 32) {
        // Load A tile 128x32 (row-major) with tf32 convert
        #pragma unroll
        for (int it = 0; it < 4; ++it) {
            int id = it*256 + tid;
            int row = id >> 3, c = (id & 7) * 4;
            float4 v = *(const float4*)(A + (size_t)(m0 + row)*K + k0 + c);
            As[row][c+0] = f2tf(v.x); As[row][c+1] = f2tf(v.y);
            As[row][c+2] = f2tf(v.z); As[row][c+3] = f2tf(v.w);
        }
        // Load B tile 32x128 with tf32 convert
        #pragma unroll
        for (int it = 0; it < 4; ++it) {
            int id = it*256 + tid;
            int krow = id >> 5, c = (id & 31) * 4;
            float4 v = *(const float4*)(Bw + (size_t)(k0 + krow)*NDIM + n0 + c);
            Bs[krow][c+0] = f2tf(v.x); Bs[krow][c+1] = f2tf(v.y);
            Bs[krow][c+2] = f2tf(v.z); Bs[krow][c+3] = f2tf(v.w);
        }
        __syncthreads();

        #pragma unroll
        for (int kc = 0; kc < 4; ++kc) {
            int kk = kc * 8;
            u32 af[4][4], bf[4][2];
            #pragma unroll
            for (int mt = 0; mt < 4; ++mt) {
                int mr = warp_m*64 + mt*16;
                af[mt][0] = As[mr + lr    ][kk + lc    ];
                af[mt][1] = As[mr + lr + 8][kk + lc    ];
                af[mt][2] = As[mr + lr    ][kk + lc + 4];
                af[mt][3] = As[mr + lr + 8][kk + lc + 4];
            }
            #pragma unroll
            for (int nt = 0; nt < 4; ++nt) {
                int nc = warp_n*32 + nt*8;
                bf[nt][0] = Bs[kk + lc    ][nc + lr];
                bf[nt][1] = Bs[kk + lc + 4][nc + lr];
            }
            #pragma unroll
            for (int mt = 0; mt < 4; ++mt)
                #pragma unroll
                for (int nt = 0; nt < 4; ++nt)
                    mma_tf32(F.c[mt][nt], af[mt][0], af[mt][1], af[mt][2], af[mt][3],
                             bf[nt][0], bf[nt][1]);
        }
        __syncthreads();
    }
}

__global__ __launch_bounds__(256) void qkv_gemm(const float* __restrict__ A,
                                                const float* __restrict__ Bw) {
    __shared__ u32 As[128][AS_STRIDE];
    __shared__ u32 Bs[32][BS_STRIDE];
    int tid = threadIdx.x;
    int lane = tid & 31, wid = tid >> 5;
    int warp_m = wid >> 2, warp_n = wid & 3;
    int lr = lane >> 2, lc = lane & 3;
    int m0 = blockIdx.y * 128, n0 = blockIdx.x * 128;

    GemmFrags F = {};
    gemm_tf32_body<NQKV>(A, Bw, As, Bs, m0, n0, F);

    // Epilogue: scatter qkv. n = (h*64+d)*3 + three
    #pragma unroll
    for (int mt = 0; mt < 4; ++mt) {
        #pragma unroll
        for (int nt = 0; nt < 4; ++nt) {
            #pragma unroll
            for (int f = 0; f < 4; ++f) {
                int m = m0 + warp_m*64 + mt*16 + lr + (f >> 1)*8;
                int n = n0 + warp_n*32 + nt*8 + lc*2 + (f & 1);
                int bb = m >> 11, t = m & 2047;       // T_ = 2048
                int three = n % 3;
                int hd = n / 3;
                int h = hd >> 6, d = hd & 63;
                size_t dst = (((size_t)(bb*H_ + h))*T_ + t)*D_ + d;
                float v = F.c[mt][nt][f];
                if (three == 0)      g_q[dst] = v;
                else if (three == 1) g_k[dst] = v;
                else                 g_v[dst] = v;
            }
        }
    }
}

__global__ __launch_bounds__(256) void proj_gemm(const float* __restrict__ Bw,
                                                 const float* __restrict__ bias,
                                                 float* __restrict__ out) {
    __shared__ u32 As[128][AS_STRIDE];
    __shared__ u32 Bs[32][BS_STRIDE];
    int tid = threadIdx.x;
    int lane = tid & 31, wid = tid >> 5;
    int warp_m = wid >> 2, warp_n = wid & 3;
    int lr = lane >> 2, lc = lane & 3;
    int m0 = blockIdx.y * 128, n0 = blockIdx.x * 128;

    GemmFrags F = {};
    gemm_tf32_body<C_>(g_att, Bw, As, Bs, m0, n0, F);

    #pragma unroll
    for (int mt = 0; mt < 4; ++mt) {
        #pragma unroll
        for (int nt = 0; nt < 4; ++nt) {
            #pragma unroll
            for (int f = 0; f < 4; ++f) {
                int m = m0 + warp_m*64 + mt*16 + lr + (f >> 1)*8;
                int n = n0 + warp_n*32 + nt*8 + lc*2 + (f & 1);
                out[(size_t)m * C_ + n] = F.c[mt][nt][f] + bias[n];
            }
        }
    }
}

// ---------------------------------------------------------------------------
// Flash attention, fp32. BQ=64 queries/block, BK=64 keys/tile, 256 threads.
// (unchanged from round 1 — round-3 target for tensorization)
// ---------------------------------------------------------------------------
#define PAD 68

__global__ __launch_bounds__(256) void attn_kernel() {
    extern __shared__ float sm[];
    float* Qt   = sm;                 // [64][PAD]  Qt[d][i]
    float* KP   = Qt + 64*PAD;        // [64][PAD]  Kt[d][j] -> Pt[j][i]
    float* Vs   = KP + 64*PAD;        // [64][PAD]  Vs[k][d]
    float* Ss   = Vs + 64*PAD;        // [64][PAD]  S[i][j]
    float* mrow = Ss + 64*PAD;        // [64]
    float* lrow = mrow + 64;          // [64]
    float* rrow = lrow + 64;          // [64]

    int tid = threadIdx.x;
    int tx = tid & 15, ty = tid >> 4;
    int bh = blockIdx.y;
    int b = bh >> 4, h = bh & 15;
    int qBase = blockIdx.x * 64;

    const float* qg  = g_q + (((size_t)(b*H_ + h))*T_ + qBase)*D_;
    const float* kgb = g_k + ((size_t)(b*H_ + h))*T_*D_;
    const float* vgb = g_v + ((size_t)(b*H_ + h))*T_*D_;

    {
        int i = tid & 63, dg = tid >> 6;
        #pragma unroll
        for (int it = 0; it < 4; ++it) {
            int d4 = (dg + it*4) * 4;
            float4 v = *(const float4*)(qg + (size_t)i*D_ + d4);
            Qt[(d4+0)*PAD + i] = v.x;
            Qt[(d4+1)*PAD + i] = v.y;
            Qt[(d4+2)*PAD + i] = v.z;
            Qt[(d4+3)*PAD + i] = v.w;
        }
    }
    if (tid < 64) { mrow[tid] = -INFINITY; lrow[tid] = 0.0f; }

    float o[4][4] = {};
    const float scale = 0.125f;
    int nkt = blockIdx.x + 1;

    for (int kt = 0; kt < nkt; ++kt) {
        int kBase = kt * 64;
        __syncthreads();

        {
            const float* kg = kgb + (size_t)kBase * D_;
            int i = tid & 63, dg = tid >> 6;
            #pragma unroll
            for (int it = 0; it < 4; ++it) {
                int d4 = (dg + it*4) * 4;
                float4 v = *(const float4*)(kg + (size_t)i*D_ + d4);
                KP[(d4+0)*PAD + i] = v.x;
                KP[(d4+1)*PAD + i] = v.y;
                KP[(d4+2)*PAD + i] = v.z;
                KP[(d4+3)*PAD + i] = v.w;
            }
            const float* vg = vgb + (size_t)kBase * D_;
            #pragma unroll
            for (int it = 0; it < 4; ++it) {
                int idx = tid + it*256;
                int kk = idx >> 4, d4 = (idx & 15) * 4;
                *(float4*)&Vs[kk*PAD + d4] = *(const float4*)(vg + (size_t)kk*D_ + d4);
            }
        }
        __syncthreads();

        {
            float c4[4][4] = {};
            #pragma unroll 16
            for (int d = 0; d < 64; ++d) {
                float4 a  = *(float4*)&Qt[d*PAD + ty*4];
                float4 bk = *(float4*)&KP[d*PAD + tx*4];
                float af[4] = {a.x, a.y, a.z, a.w};
                float bf[4] = {bk.x, bk.y, bk.z, bk.w};
                #pragma unroll
                for (int i = 0; i < 4; ++i)
                    #pragma unroll
                    for (int j = 0; j < 4; ++j)
                        c4[i][j] += af[i] * bf[j];
            }
            #pragma unroll
            for (int i = 0; i < 4; ++i) {
                int qi = qBase + ty*4 + i;
                #pragma unroll
                for (int j = 0; j < 4; ++j) {
                    int kj = kBase + tx*4 + j;
                    Ss[(ty*4+i)*PAD + tx*4+j] = (kj <= qi) ? c4[i][j]*scale : -INFINITY;
                }
            }
        }
        __syncthreads();

        {
            int row = tid >> 2, g = tid & 3;
            float sv[16];
            float lm = -INFINITY;
            #pragma unroll
            for (int j = 0; j < 16; ++j) {
                sv[j] = Ss[row*PAD + g*16 + j];
                lm = fmaxf(lm, sv[j]);
            }
            lm = fmaxf(lm, __shfl_xor_sync(0xffffffffu, lm, 1));
            lm = fmaxf(lm, __shfl_xor_sync(0xffffffffu, lm, 2));
            float newm = fmaxf(mrow[row], lm);
            float ls = 0.0f;
            #pragma unroll
            for (int j = 0; j < 16; ++j) {
                float p = __expf(sv[j] - newm);
                ls += p;
                KP[(g*16+j)*PAD + row] = p;
            }
            ls += __shfl_xor_sync(0xffffffffu, ls, 1);
            ls += __shfl_xor_sync(0xffffffffu, ls, 2);
            if (g == 0) {
                float r = __expf(mrow[row] - newm);
                rrow[row] = r;
                lrow[row] = lrow[row] * r + ls;
                mrow[row] = newm;
            }
        }
        __syncthreads();

        {
            float rr[4];
            #pragma unroll
            for (int i = 0; i < 4; ++i) rr[i] = rrow[ty*4 + i];
            #pragma unroll
            for (int i = 0; i < 4; ++i)
                #pragma unroll
                for (int j = 0; j < 4; ++j)
                    o[i][j] *= rr[i];
            #pragma unroll 16
            for (int k = 0; k < 64; ++k) {
                float4 a = *(float4*)&KP[k*PAD + ty*4];
                float4 v = *(float4*)&Vs[k*PAD + tx*4];
                float af[4] = {a.x, a.y, a.z, a.w};
                float vf[4] = {v.x, v.y, v.z, v.w};
                #pragma unroll
                for (int i = 0; i < 4; ++i)
                    #pragma unroll
                    for (int j = 0; j < 4; ++j)
                        o[i][j] += af[i] * vf[j];
            }
        }
    }

    #pragma unroll
    for (int i = 0; i < 4; ++i) {
        int qi = ty*4 + i;
        float inv = 1.0f / lrow[qi];
        int t = qBase + qi;
        float* og = g_att + (((size_t)(b*T_ + t))*H_ + h)*D_ + tx*4;
        float4 w;
        w.x = o[i][0]*inv; w.y = o[i][1]*inv; w.z = o[i][2]*inv; w.w = o[i][3]*inv;
        *(float4*)og = w;
    }
}

// ---------------------------------------------------------------------------
extern "C" void kernel_launch(void* const* d_in, const int* in_sizes, int n_in,
                              void* d_out, int out_size) {
    const float* x      = (const float*)d_in[0];
    const float* w_qkv  = (const float*)d_in[1];
    const float* w_proj = (const float*)d_in[2];
    const float* b_proj = (const float*)d_in[3];
    float* out = (float*)d_out;

    const int ATTN_SMEM = (4*64*PAD + 3*64) * (int)sizeof(float);  // 70400 B
    cudaFuncSetAttribute(attn_kernel,
                         cudaFuncAttributeMaxDynamicSharedMemorySize, ATTN_SMEM);

    qkv_gemm<<<dim3(NQKV/128, M_/128), 256>>>(x, w_qkv);
    attn_kernel<<<dim3(T_/64, B_*H_), 256, ATTN_SMEM>>>();
    proj_gemm<<<dim3(C_/128, M_/128), 256>>>(w_proj, b_proj, out);
}

// round 4
// speedup vs baseline: 2.7621x; 1.6829x over previous
#include <cuda_runtime.h>
#include <math.h>

#define B_ 2
#define T_ 2048
#define C_ 1024
#define H_ 16
#define D_ 64
#define M_ (B_*T_)          // 4096
#define NQKV (3*C_)         // 3072

typedef unsigned int u32;

// Scratch (allocation-free rule: __device__ globals)
__device__ float g_q[(size_t)B_*H_*T_*D_];
__device__ float g_k[(size_t)B_*H_*T_*D_];
__device__ float g_v[(size_t)B_*H_*T_*D_];
__device__ float g_att[(size_t)M_*C_];   // [b][t][h][d] == [M, C] row-major

__device__ __forceinline__ u32 f2tf(float x) {
    u32 r; asm("cvt.rna.tf32.f32 %0, %1;" : "=r"(r) : "f"(x)); return r;
}
__device__ __forceinline__ void mma_tf32(float c[4], u32 a0, u32 a1, u32 a2, u32 a3,
                                         u32 b0, u32 b1) {
    asm volatile("mma.sync.aligned.m16n8k8.row.col.f32.tf32.tf32.f32 "
                 "{%0,%1,%2,%3}, {%4,%5,%6,%7}, {%8,%9}, {%0,%1,%2,%3};"
                 : "+f"(c[0]), "+f"(c[1]), "+f"(c[2]), "+f"(c[3])
                 : "r"(a0), "r"(a1), "r"(a2), "r"(a3), "r"(b0), "r"(b1));
}

// ---------------------------------------------------------------------------
// tf32 tensor-core GEMM: 128x128 tile, BK=32, 256 threads (8 warps, 2m x 4n,
// each warp 64x32 via 4x4 m16n8k8 tiles). A,B converted to tf32 at smem store.
// ---------------------------------------------------------------------------
#define AS_STRIDE 36
#define BS_STRIDE 132

struct GemmFrags { float c[4][4][4]; };   // [mt][nt][frag]

template<int NDIM>
__device__ __forceinline__ void gemm_tf32_body(const float* __restrict__ A,
                                               const float* __restrict__ Bw,
                                               u32 (*As)[AS_STRIDE],
                                               u32 (*Bs)[BS_STRIDE],
                                               int m0, int n0, GemmFrags& F) {
    const int K = C_;
    int tid = threadIdx.x;
    int lane = tid & 31, wid = tid >> 5;
    int warp_m = wid >> 2, warp_n = wid & 3;    // 2 x 4
    int lr = lane >> 2, lc = lane & 3;

    for (int k0 = 0; k0 < K; k0 += 32) {
        #pragma unroll
        for (int it = 0; it < 4; ++it) {
            int id = it*256 + tid;
            int row = id >> 3, c = (id & 7) * 4;
            float4 v = *(const float4*)(A + (size_t)(m0 + row)*K + k0 + c);
            As[row][c+0] = f2tf(v.x); As[row][c+1] = f2tf(v.y);
            As[row][c+2] = f2tf(v.z); As[row][c+3] = f2tf(v.w);
        }
        #pragma unroll
        for (int it = 0; it < 4; ++it) {
            int id = it*256 + tid;
            int krow = id >> 5, c = (id & 31) * 4;
            float4 v = *(const float4*)(Bw + (size_t)(k0 + krow)*NDIM + n0 + c);
            Bs[krow][c+0] = f2tf(v.x); Bs[krow][c+1] = f2tf(v.y);
            Bs[krow][c+2] = f2tf(v.z); Bs[krow][c+3] = f2tf(v.w);
        }
        __syncthreads();

        #pragma unroll
        for (int kc = 0; kc < 4; ++kc) {
            int kk = kc * 8;
            u32 af[4][4], bf[4][2];
            #pragma unroll
            for (int mt = 0; mt < 4; ++mt) {
                int mr = warp_m*64 + mt*16;
                af[mt][0] = As[mr + lr    ][kk + lc    ];
                af[mt][1] = As[mr + lr + 8][kk + lc    ];
                af[mt][2] = As[mr + lr    ][kk + lc + 4];
                af[mt][3] = As[mr + lr + 8][kk + lc + 4];
            }
            #pragma unroll
            for (int nt = 0; nt < 4; ++nt) {
                int nc = warp_n*32 + nt*8;
                bf[nt][0] = Bs[kk + lc    ][nc + lr];
                bf[nt][1] = Bs[kk + lc + 4][nc + lr];
            }
            #pragma unroll
            for (int mt = 0; mt < 4; ++mt)
                #pragma unroll
                for (int nt = 0; nt < 4; ++nt)
                    mma_tf32(F.c[mt][nt], af[mt][0], af[mt][1], af[mt][2], af[mt][3],
                             bf[nt][0], bf[nt][1]);
        }
        __syncthreads();
    }
}

__global__ __launch_bounds__(256) void qkv_gemm(const float* __restrict__ A,
                                                const float* __restrict__ Bw) {
    __shared__ u32 As[128][AS_STRIDE];
    __shared__ u32 Bs[32][BS_STRIDE];
    int tid = threadIdx.x;
    int lane = tid & 31, wid = tid >> 5;
    int warp_m = wid >> 2, warp_n = wid & 3;
    int lr = lane >> 2, lc = lane & 3;
    int m0 = blockIdx.y * 128, n0 = blockIdx.x * 128;

    GemmFrags F = {};
    gemm_tf32_body<NQKV>(A, Bw, As, Bs, m0, n0, F);

    #pragma unroll
    for (int mt = 0; mt < 4; ++mt) {
        #pragma unroll
        for (int nt = 0; nt < 4; ++nt) {
            #pragma unroll
            for (int f = 0; f < 4; ++f) {
                int m = m0 + warp_m*64 + mt*16 + lr + (f >> 1)*8;
                int n = n0 + warp_n*32 + nt*8 + lc*2 + (f & 1);
                int bb = m >> 11, t = m & 2047;
                int three = n % 3;
                int hd = n / 3;
                int h = hd >> 6, d = hd & 63;
                size_t dst = (((size_t)(bb*H_ + h))*T_ + t)*D_ + d;
                float v = F.c[mt][nt][f];
                if (three == 0)      g_q[dst] = v;
                else if (three == 1) g_k[dst] = v;
                else                 g_v[dst] = v;
            }
        }
    }
}

__global__ __launch_bounds__(256) void proj_gemm(const float* __restrict__ Bw,
                                                 const float* __restrict__ bias,
                                                 float* __restrict__ out) {
    __shared__ u32 As[128][AS_STRIDE];
    __shared__ u32 Bs[32][BS_STRIDE];
    int tid = threadIdx.x;
    int lane = tid & 31, wid = tid >> 5;
    int warp_m = wid >> 2, warp_n = wid & 3;
    int lr = lane >> 2, lc = lane & 3;
    int m0 = blockIdx.y * 128, n0 = blockIdx.x * 128;

    GemmFrags F = {};
    gemm_tf32_body<C_>(g_att, Bw, As, Bs, m0, n0, F);

    #pragma unroll
    for (int mt = 0; mt < 4; ++mt) {
        #pragma unroll
        for (int nt = 0; nt < 4; ++nt) {
            #pragma unroll
            for (int f = 0; f < 4; ++f) {
                int m = m0 + warp_m*64 + mt*16 + lr + (f >> 1)*8;
                int n = n0 + warp_n*32 + nt*8 + lc*2 + (f & 1);
                out[(size_t)m * C_ + n] = F.c[mt][nt][f] + bias[n];
            }
        }
    }
}

// ---------------------------------------------------------------------------
// Flash attention with tf32 tensor-core matmul phases.
// BQ=64, BK=64, 256 threads = 8 warps as 4(m) x 2(n).
// Strides: QS=68 (== 4 mod 32: bank = lane for lr-row-indexed frag loads),
//          VS=72 (== 8 mod 32: bank = lc*8+lr for lc-row-indexed B loads).
// Ss (fp32 scores) aliases Ps (tf32 probs): softmax threads read exactly the
// elements they overwrite.
// ---------------------------------------------------------------------------
#define QS 68
#define VSS 72

__global__ __launch_bounds__(256) void attn_kernel() {
    extern __shared__ char smc[];
    u32* Qs = (u32*)smc;                 // [64][QS]  tf32 Q[q][d]
    u32* Ks = Qs + 64*QS;                // [64][QS]  tf32 K[key][d]
    u32* Vs = Ks + 64*QS;                // [64][VSS] tf32 V[key][d]
    float* Ss = (float*)(Vs + 64*VSS);   // [64][QS]  fp32 S[q][key], aliased:
    u32* Ps = (u32*)Ss;                  //           tf32 P[q][key]
    float* mrow = Ss + 64*QS;            // [64]
    float* lrow = mrow + 64;
    float* rrow = lrow + 64;

    int tid = threadIdx.x;
    int lane = tid & 31, wid = tid >> 5;
    int warp_m = wid >> 1, warp_n = wid & 1;
    int lr = lane >> 2, lc = lane & 3;
    int mr = warp_m * 16;

    int bh = blockIdx.y;
    int b = bh >> 4, h = bh & 15;
    int qBase = blockIdx.x * 64;

    const float* qg  = g_q + (((size_t)(b*H_ + h))*T_ + qBase)*D_;
    const float* kgb = g_k + ((size_t)(b*H_ + h))*T_*D_;
    const float* vgb = g_v + ((size_t)(b*H_ + h))*T_*D_;

    // Load Q tile (tf32 convert)
    #pragma unroll
    for (int it = 0; it < 4; ++it) {
        int id = it*256 + tid;
        int row = id >> 4, c = (id & 15) * 4;
        float4 v = *(const float4*)(qg + (size_t)row*D_ + c);
        Qs[row*QS + c+0] = f2tf(v.x); Qs[row*QS + c+1] = f2tf(v.y);
        Qs[row*QS + c+2] = f2tf(v.z); Qs[row*QS + c+3] = f2tf(v.w);
    }
    if (tid < 64) { mrow[tid] = -INFINITY; lrow[tid] = 0.0f; }

    float o[4][4] = {};               // [nt][frag] persistent O accumulator
    const float scale = 0.125f;       // D^-0.5
    int nkt = blockIdx.x + 1;         // causal tile skip

    for (int kt = 0; kt < nkt; ++kt) {
        int kBase = kt * 64;
        __syncthreads();   // prior phase-C readers done (and Qt visible, iter 0)

        // Load K, V tiles (tf32 convert)
        #pragma unroll
        for (int it = 0; it < 4; ++it) {
            int id = it*256 + tid;
            int row = id >> 4, c = (id & 15) * 4;
            float4 kv = *(const float4*)(kgb + (size_t)(kBase + row)*D_ + c);
            Ks[row*QS + c+0] = f2tf(kv.x); Ks[row*QS + c+1] = f2tf(kv.y);
            Ks[row*QS + c+2] = f2tf(kv.z); Ks[row*QS + c+3] = f2tf(kv.w);
            float4 vv = *(const float4*)(vgb + (size_t)(kBase + row)*D_ + c);
            Vs[row*VSS + c+0] = f2tf(vv.x); Vs[row*VSS + c+1] = f2tf(vv.y);
            Vs[row*VSS + c+2] = f2tf(vv.z); Vs[row*VSS + c+3] = f2tf(vv.w);
        }
        __syncthreads();

        // Phase A: S = Q K^T  (tensor)
        {
            float sacc[4][4] = {};
            #pragma unroll
            for (int kk = 0; kk < 64; kk += 8) {
                u32 a0 = Qs[(mr+lr  )*QS + kk+lc  ];
                u32 a1 = Qs[(mr+lr+8)*QS + kk+lc  ];
                u32 a2 = Qs[(mr+lr  )*QS + kk+lc+4];
                u32 a3 = Qs[(mr+lr+8)*QS + kk+lc+4];
                #pragma unroll
                for (int nt = 0; nt < 4; ++nt) {
                    int nc = warp_n*32 + nt*8;
                    u32 b0 = Ks[(nc+lr)*QS + kk+lc  ];
                    u32 b1 = Ks[(nc+lr)*QS + kk+lc+4];
                    mma_tf32(sacc[nt], a0, a1, a2, a3, b0, b1);
                }
            }
            #pragma unroll
            for (int nt = 0; nt < 4; ++nt) {
                int nc = warp_n*32 + nt*8;
                #pragma unroll
                for (int f = 0; f < 4; ++f) {
                    int row = mr + lr + (f >> 1)*8;
                    int col = nc + lc*2 + (f & 1);
                    int qi = qBase + row, kj = kBase + col;
                    Ss[row*QS + col] = (kj <= qi) ? sacc[nt][f]*scale : -INFINITY;
                }
            }
        }
        __syncthreads();

        // Phase B: online softmax; P (tf32) overwrites S in place
        {
            int row = tid >> 2, g = tid & 3;
            float sv[16];
            float lm = -INFINITY;
            #pragma unroll
            for (int j = 0; j < 16; ++j) {
                sv[j] = Ss[row*QS + g*16 + j];
                lm = fmaxf(lm, sv[j]);
            }
            lm = fmaxf(lm, __shfl_xor_sync(0xffffffffu, lm, 1));
            lm = fmaxf(lm, __shfl_xor_sync(0xffffffffu, lm, 2));
            float newm = fmaxf(mrow[row], lm);
            float ls = 0.0f;
            #pragma unroll
            for (int j = 0; j < 16; ++j) {
                float p = __expf(sv[j] - newm);
                ls += p;
                Ps[row*QS + g*16 + j] = f2tf(p);
            }
            ls += __shfl_xor_sync(0xffffffffu, ls, 1);
            ls += __shfl_xor_sync(0xffffffffu, ls, 2);
            if (g == 0) {
                float r = __expf(mrow[row] - newm);
                rrow[row] = r;
                lrow[row] = lrow[row] * r + ls;
                mrow[row] = newm;
            }
        }
        __syncthreads();

        // Phase C: O = O*r + P V  (tensor)
        {
            float r0 = rrow[mr + lr], r1 = rrow[mr + lr + 8];
            #pragma unroll
            for (int nt = 0; nt < 4; ++nt) {
                o[nt][0] *= r0; o[nt][1] *= r0;
                o[nt][2] *= r1; o[nt][3] *= r1;
            }
            #pragma unroll
            for (int kk = 0; kk < 64; kk += 8) {
                u32 a0 = Ps[(mr+lr  )*QS + kk+lc  ];
                u32 a1 = Ps[(mr+lr+8)*QS + kk+lc  ];
                u32 a2 = Ps[(mr+lr  )*QS + kk+lc+4];
                u32 a3 = Ps[(mr+lr+8)*QS + kk+lc+4];
                #pragma unroll
                for (int nt = 0; nt < 4; ++nt) {
                    int nc = warp_n*32 + nt*8;
                    u32 b0 = Vs[(kk+lc  )*VSS + nc+lr];
                    u32 b1 = Vs[(kk+lc+4)*VSS + nc+lr];
                    mma_tf32(o[nt], a0, a1, a2, a3, b0, b1);
                }
            }
        }
    }

    // Epilogue: normalize, write [b][t][h][d]
    #pragma unroll
    for (int half = 0; half < 2; ++half) {
        int row = mr + lr + half*8;
        float inv = 1.0f / lrow[row];
        int t = qBase + row;
        float* og = g_att + (((size_t)(b*T_ + t))*H_ + h)*D_;
        #pragma unroll
        for (int nt = 0; nt < 4; ++nt) {
            int d = warp_n*32 + nt*8 + lc*2;
            float2 w;
            w.x = o[nt][half*2+0] * inv;
            w.y = o[nt][half*2+1] * inv;
            *(float2*)(og + d) = w;
        }
    }
}

// ---------------------------------------------------------------------------
extern "C" void kernel_launch(void* const* d_in, const int* in_sizes, int n_in,
                              void* d_out, int out_size) {
    const float* x      = (const float*)d_in[0];
    const float* w_qkv  = (const float*)d_in[1];
    const float* w_proj = (const float*)d_in[2];
    const float* b_proj = (const float*)d_in[3];
    float* out = (float*)d_out;

    // (3*64*QS + 64*VSS)*4 + 64*QS*4 + 3*64*4
    const int ATTN_SMEM = (64*QS*3 + 64*VSS)*4 + 3*64*4;   // 71424 B
    cudaFuncSetAttribute(attn_kernel,
                         cudaFuncAttributeMaxDynamicSharedMemorySize, ATTN_SMEM);

    qkv_gemm<<<dim3(NQKV/128, M_/128), 256>>>(x, w_qkv);
    attn_kernel<<<dim3(T_/64, B_*H_), 256, ATTN_SMEM>>>();
    proj_gemm<<<dim3(C_/128, M_/128), 256>>>(w_proj, b_proj, out);
}

// round 5
// speedup vs baseline: 2.8317x; 1.0252x over previous
#include <cuda_runtime.h>
#include <math.h>

#define B_ 2
#define T_ 2048
#define C_ 1024
#define H_ 16
#define D_ 64
#define M_ (B_*T_)          // 4096
#define NQKV (3*C_)         // 3072

typedef unsigned int u32;

// Scratch (allocation-free rule: __device__ globals)
__device__ float g_q[(size_t)B_*H_*T_*D_];
__device__ float g_k[(size_t)B_*H_*T_*D_];
__device__ float g_v[(size_t)B_*H_*T_*D_];
__device__ float g_att[(size_t)M_*C_];     // [b][t][h][d] == [M, C], tf32-grid values
__device__ float g_xr[(size_t)M_*C_];      // tf32-rounded x
__device__ float g_wq[(size_t)C_*NQKV];    // tf32-rounded w_qkv
__device__ float g_wp[(size_t)C_*C_];      // tf32-rounded w_proj

__device__ __forceinline__ u32 f2tf(float x) {
    u32 r; asm("cvt.rna.tf32.f32 %0, %1;" : "=r"(r) : "f"(x)); return r;
}
__device__ __forceinline__ float f2tff(float x) {
    return __uint_as_float(f2tf(x));
}
__device__ __forceinline__ void mma_tf32(float c[4], u32 a0, u32 a1, u32 a2, u32 a3,
                                         u32 b0, u32 b1) {
    asm volatile("mma.sync.aligned.m16n8k8.row.col.f32.tf32.tf32.f32 "
                 "{%0,%1,%2,%3}, {%4,%5,%6,%7}, {%8,%9}, {%0,%1,%2,%3};"
                 : "+f"(c[0]), "+f"(c[1]), "+f"(c[2]), "+f"(c[3])
                 : "r"(a0), "r"(a1), "r"(a2), "r"(a3), "r"(b0), "r"(b1));
}
__device__ __forceinline__ void cp16(u32* smem, const void* gmem) {
    u32 s = (u32)__cvta_generic_to_shared(smem);
    asm volatile("cp.async.cg.shared.global [%0], [%1], 16;\n" :: "r"(s), "l"(gmem));
}

// ---------------------------------------------------------------------------
// Prep: round arrays to the tf32 grid (so cp.async'd raw bytes are exact
// under mma's hardware truncation).
// ---------------------------------------------------------------------------
__global__ void round_tf32(const float4* __restrict__ s, float4* __restrict__ d, int n4) {
    int i = blockIdx.x * blockDim.x + threadIdx.x;
    if (i < n4) {
        float4 v = s[i];
        float4 r;
        r.x = f2tff(v.x); r.y = f2tff(v.y); r.z = f2tff(v.z); r.w = f2tff(v.w);
        d[i] = r;
    }
}

// ---------------------------------------------------------------------------
// tf32 tensor-core GEMM: 128x128 tile, BK=32, 256 threads (8 warps 2m x 4n),
// cp.async 2-stage double-buffered smem pipeline. A,B pre-rounded to tf32.
// ---------------------------------------------------------------------------
#define AS_STRIDE 36
#define BS_STRIDE 132
#define NIT (C_/32)

struct GemmFrags { float c[4][4][4]; };   // [mt][nt][frag]

template<int NDIM>
__device__ __forceinline__ void gemm_cp_body(const float* __restrict__ A,
                                             const float* __restrict__ Bw,
                                             u32* As, u32* Bs,
                                             int m0, int n0, GemmFrags& F) {
    int tid = threadIdx.x;
    int lane = tid & 31, wid = tid >> 5;
    int warp_m = wid >> 2, warp_n = wid & 3;    // 2 x 4
    int lr = lane >> 2, lc = lane & 3;

    auto issue = [&](int k0, int b) {
        u32* Ab = As + b * 128 * AS_STRIDE;
        u32* Bb = Bs + b * 32 * BS_STRIDE;
        #pragma unroll
        for (int it = 0; it < 4; ++it) {
            int id = it*256 + tid;
            int row = id >> 3, c = (id & 7) * 4;
            cp16(Ab + row*AS_STRIDE + c, A + (size_t)(m0 + row)*C_ + k0 + c);
        }
        #pragma unroll
        for (int it = 0; it < 4; ++it) {
            int id = it*256 + tid;
            int krow = id >> 5, c = (id & 31) * 4;
            cp16(Bb + krow*BS_STRIDE + c, Bw + (size_t)(k0 + krow)*NDIM + n0 + c);
        }
        asm volatile("cp.async.commit_group;\n");
    };

    issue(0, 0);
    for (int it = 0; it < NIT; ++it) {
        if (it + 1 < NIT) {
            issue((it+1)*32, (it+1) & 1);
            asm volatile("cp.async.wait_group 1;\n");
        } else {
            asm volatile("cp.async.wait_group 0;\n");
        }
        __syncthreads();
        u32* Ab = As + (it & 1) * 128 * AS_STRIDE;
        u32* Bb = Bs + (it & 1) * 32 * BS_STRIDE;
        #pragma unroll
        for (int kc = 0; kc < 4; ++kc) {
            int kk = kc * 8;
            u32 af[4][4], bf[4][2];
            #pragma unroll
            for (int mt = 0; mt < 4; ++mt) {
                int mr = warp_m*64 + mt*16;
                af[mt][0] = Ab[(mr + lr    )*AS_STRIDE + kk + lc    ];
                af[mt][1] = Ab[(mr + lr + 8)*AS_STRIDE + kk + lc    ];
                af[mt][2] = Ab[(mr + lr    )*AS_STRIDE + kk + lc + 4];
                af[mt][3] = Ab[(mr + lr + 8)*AS_STRIDE + kk + lc + 4];
            }
            #pragma unroll
            for (int nt = 0; nt < 4; ++nt) {
                int nc = warp_n*32 + nt*8;
                bf[nt][0] = Bb[(kk + lc    )*BS_STRIDE + nc + lr];
                bf[nt][1] = Bb[(kk + lc + 4)*BS_STRIDE + nc + lr];
            }
            #pragma unroll
            for (int mt = 0; mt < 4; ++mt)
                #pragma unroll
                for (int nt = 0; nt < 4; ++nt)
                    mma_tf32(F.c[mt][nt], af[mt][0], af[mt][1], af[mt][2], af[mt][3],
                             bf[nt][0], bf[nt][1]);
        }
        __syncthreads();
    }
}

#define GEMM_SMEM ((2*(128*AS_STRIDE + 32*BS_STRIDE)) * 4)   // 70656 B

__global__ __launch_bounds__(256) void qkv_gemm() {
    extern __shared__ u32 smg[];
    u32* As = smg;
    u32* Bs = smg + 2*128*AS_STRIDE;
    int tid = threadIdx.x;
    int lane = tid & 31, wid = tid >> 5;
    int warp_m = wid >> 2, warp_n = wid & 3;
    int lr = lane >> 2, lc = lane & 3;
    int m0 = blockIdx.y * 128, n0 = blockIdx.x * 128;

    GemmFrags F = {};
    gemm_cp_body<NQKV>(g_xr, g_wq, As, Bs, m0, n0, F);

    #pragma unroll
    for (int mt = 0; mt < 4; ++mt) {
        #pragma unroll
        for (int nt = 0; nt < 4; ++nt) {
            #pragma unroll
            for (int f = 0; f < 4; ++f) {
                int m = m0 + warp_m*64 + mt*16 + lr + (f >> 1)*8;
                int n = n0 + warp_n*32 + nt*8 + lc*2 + (f & 1);
                int bb = m >> 11, t = m & 2047;
                int three = n % 3;
                int hd = n / 3;
                int h = hd >> 6, d = hd & 63;
                size_t dst = (((size_t)(bb*H_ + h))*T_ + t)*D_ + d;
                float v = F.c[mt][nt][f];
                if (three == 0)      g_q[dst] = v;
                else if (three == 1) g_k[dst] = v;
                else                 g_v[dst] = v;
            }
        }
    }
}

__global__ __launch_bounds__(256) void proj_gemm(const float* __restrict__ bias,
                                                 float* __restrict__ out) {
    extern __shared__ u32 smg[];
    u32* As = smg;
    u32* Bs = smg + 2*128*AS_STRIDE;
    int tid = threadIdx.x;
    int lane = tid & 31, wid = tid >> 5;
    int warp_m = wid >> 2, warp_n = wid & 3;
    int lr = lane >> 2, lc = lane & 3;
    int m0 = blockIdx.y * 128, n0 = blockIdx.x * 128;

    GemmFrags F = {};
    gemm_cp_body<C_>(g_att, g_wp, As, Bs, m0, n0, F);

    #pragma unroll
    for (int mt = 0; mt < 4; ++mt) {
        #pragma unroll
        for (int nt = 0; nt < 4; ++nt) {
            #pragma unroll
            for (int f = 0; f < 4; ++f) {
                int m = m0 + warp_m*64 + mt*16 + lr + (f >> 1)*8;
                int n = n0 + warp_n*32 + nt*8 + lc*2 + (f & 1);
                out[(size_t)m * C_ + n] = F.c[mt][nt][f] + bias[n];
            }
        }
    }
}

// ---------------------------------------------------------------------------
// Flash attention with tf32 tensor-core matmul phases (round-4 design).
// Epilogue writes tf32-grid values so proj_gemm can consume raw bytes.
// ---------------------------------------------------------------------------
#define QS 68
#define VSS 72

__global__ __launch_bounds__(256) void attn_kernel() {
    extern __shared__ char smc[];
    u32* Qs = (u32*)smc;                 // [64][QS]  tf32 Q[q][d]
    u32* Ks = Qs + 64*QS;                // [64][QS]  tf32 K[key][d]
    u32* Vs = Ks + 64*QS;                // [64][VSS] tf32 V[key][d]
    float* Ss = (float*)(Vs + 64*VSS);   // [64][QS]  fp32 S, aliased with:
    u32* Ps = (u32*)Ss;                  //           tf32 P
    float* mrow = Ss + 64*QS;            // [64]
    float* lrow = mrow + 64;
    float* rrow = lrow + 64;

    int tid = threadIdx.x;
    int lane = tid & 31, wid = tid >> 5;
    int warp_m = wid >> 1, warp_n = wid & 1;
    int lr = lane >> 2, lc = lane & 3;
    int mr = warp_m * 16;

    int bh = blockIdx.y;
    int b = bh >> 4, h = bh & 15;
    int qBase = blockIdx.x * 64;

    const float* qg  = g_q + (((size_t)(b*H_ + h))*T_ + qBase)*D_;
    const float* kgb = g_k + ((size_t)(b*H_ + h))*T_*D_;
    const float* vgb = g_v + ((size_t)(b*H_ + h))*T_*D_;

    #pragma unroll
    for (int it = 0; it < 4; ++it) {
        int id = it*256 + tid;
        int row = id >> 4, c = (id & 15) * 4;
        float4 v = *(const float4*)(qg + (size_t)row*D_ + c);
        Qs[row*QS + c+0] = f2tf(v.x); Qs[row*QS + c+1] = f2tf(v.y);
        Qs[row*QS + c+2] = f2tf(v.z); Qs[row*QS + c+3] = f2tf(v.w);
    }
    if (tid < 64) { mrow[tid] = -INFINITY; lrow[tid] = 0.0f; }

    float o[4][4] = {};
    const float scale = 0.125f;
    int nkt = blockIdx.x + 1;

    for (int kt = 0; kt < nkt; ++kt) {
        int kBase = kt * 64;
        __syncthreads();

        #pragma unroll
        for (int it = 0; it < 4; ++it) {
            int id = it*256 + tid;
            int row = id >> 4, c = (id & 15) * 4;
            float4 kv = *(const float4*)(kgb + (size_t)(kBase + row)*D_ + c);
            Ks[row*QS + c+0] = f2tf(kv.x); Ks[row*QS + c+1] = f2tf(kv.y);
            Ks[row*QS + c+2] = f2tf(kv.z); Ks[row*QS + c+3] = f2tf(kv.w);
            float4 vv = *(const float4*)(vgb + (size_t)(kBase + row)*D_ + c);
            Vs[row*VSS + c+0] = f2tf(vv.x); Vs[row*VSS + c+1] = f2tf(vv.y);
            Vs[row*VSS + c+2] = f2tf(vv.z); Vs[row*VSS + c+3] = f2tf(vv.w);
        }
        __syncthreads();

        // Phase A: S = Q K^T
        {
            float sacc[4][4] = {};
            #pragma unroll
            for (int kk = 0; kk < 64; kk += 8) {
                u32 a0 = Qs[(mr+lr  )*QS + kk+lc  ];
                u32 a1 = Qs[(mr+lr+8)*QS + kk+lc  ];
                u32 a2 = Qs[(mr+lr  )*QS + kk+lc+4];
                u32 a3 = Qs[(mr+lr+8)*QS + kk+lc+4];
                #pragma unroll
                for (int nt = 0; nt < 4; ++nt) {
                    int nc = warp_n*32 + nt*8;
                    u32 b0 = Ks[(nc+lr)*QS + kk+lc  ];
                    u32 b1 = Ks[(nc+lr)*QS + kk+lc+4];
                    mma_tf32(sacc[nt], a0, a1, a2, a3, b0, b1);
                }
            }
            #pragma unroll
            for (int nt = 0; nt < 4; ++nt) {
                int nc = warp_n*32 + nt*8;
                #pragma unroll
                for (int f = 0; f < 4; ++f) {
                    int row = mr + lr + (f >> 1)*8;
                    int col = nc + lc*2 + (f & 1);
                    int qi = qBase + row, kj = kBase + col;
                    Ss[row*QS + col] = (kj <= qi) ? sacc[nt][f]*scale : -INFINITY;
                }
            }
        }
        __syncthreads();

        // Phase B: online softmax; P (tf32) overwrites S in place
        {
            int row = tid >> 2, g = tid & 3;
            float sv[16];
            float lm = -INFINITY;
            #pragma unroll
            for (int j = 0; j < 16; ++j) {
                sv[j] = Ss[row*QS + g*16 + j];
                lm = fmaxf(lm, sv[j]);
            }
            lm = fmaxf(lm, __shfl_xor_sync(0xffffffffu, lm, 1));
            lm = fmaxf(lm, __shfl_xor_sync(0xffffffffu, lm, 2));
            float newm = fmaxf(mrow[row], lm);
            float ls = 0.0f;
            #pragma unroll
            for (int j = 0; j < 16; ++j) {
                float p = __expf(sv[j] - newm);
                ls += p;
                Ps[row*QS + g*16 + j] = f2tf(p);
            }
            ls += __shfl_xor_sync(0xffffffffu, ls, 1);
            ls += __shfl_xor_sync(0xffffffffu, ls, 2);
            if (g == 0) {
                float r = __expf(mrow[row] - newm);
                rrow[row] = r;
                lrow[row] = lrow[row] * r + ls;
                mrow[row] = newm;
            }
        }
        __syncthreads();

        // Phase C: O = O*r + P V
        {
            float r0 = rrow[mr + lr], r1 = rrow[mr + lr + 8];
            #pragma unroll
            for (int nt = 0; nt < 4; ++nt) {
                o[nt][0] *= r0; o[nt][1] *= r0;
                o[nt][2] *= r1; o[nt][3] *= r1;
            }
            #pragma unroll
            for (int kk = 0; kk < 64; kk += 8) {
                u32 a0 = Ps[(mr+lr  )*QS + kk+lc  ];
                u32 a1 = Ps[(mr+lr+8)*QS + kk+lc  ];
                u32 a2 = Ps[(mr+lr  )*QS + kk+lc+4];
                u32 a3 = Ps[(mr+lr+8)*QS + kk+lc+4];
                #pragma unroll
                for (int nt = 0; nt < 4; ++nt) {
                    int nc = warp_n*32 + nt*8;
                    u32 b0 = Vs[(kk+lc  )*VSS + nc+lr];
                    u32 b1 = Vs[(kk+lc+4)*VSS + nc+lr];
                    mma_tf32(o[nt], a0, a1, a2, a3, b0, b1);
                }
            }
        }
    }

    // Epilogue: normalize, round to tf32 grid, write [b][t][h][d]
    #pragma unroll
    for (int half = 0; half < 2; ++half) {
        int row = mr + lr + half*8;
        float inv = 1.0f / lrow[row];
        int t = qBase + row;
        float* og = g_att + (((size_t)(b*T_ + t))*H_ + h)*D_;
        #pragma unroll
        for (int nt = 0; nt < 4; ++nt) {
            int d = warp_n*32 + nt*8 + lc*2;
            float2 w;
            w.x = f2tff(o[nt][half*2+0] * inv);
            w.y = f2tff(o[nt][half*2+1] * inv);
            *(float2*)(og + d) = w;
        }
    }
}

// ---------------------------------------------------------------------------
extern "C" void kernel_launch(void* const* d_in, const int* in_sizes, int n_in,
                              void* d_out, int out_size) {
    const float* x      = (const float*)d_in[0];
    const float* w_qkv  = (const float*)d_in[1];
    const float* w_proj = (const float*)d_in[2];
    const float* b_proj = (const float*)d_in[3];
    float* out = (float*)d_out;

    const int ATTN_SMEM = (64*QS*3 + 64*VSS)*4 + 3*64*4;
    cudaFuncSetAttribute(attn_kernel,
                         cudaFuncAttributeMaxDynamicSharedMemorySize, ATTN_SMEM);
    cudaFuncSetAttribute(qkv_gemm,
                         cudaFuncAttributeMaxDynamicSharedMemorySize, GEMM_SMEM);
    cudaFuncSetAttribute(proj_gemm,
                         cudaFuncAttributeMaxDynamicSharedMemorySize, GEMM_SMEM);

    float *g_xr_p, *g_wq_p, *g_wp_p;
    cudaGetSymbolAddress((void**)&g_xr_p, g_xr);
    cudaGetSymbolAddress((void**)&g_wq_p, g_wq);
    cudaGetSymbolAddress((void**)&g_wp_p, g_wp);

    int n4x = M_*C_/4, n4q = C_*NQKV/4, n4p = C_*C_/4;
    round_tf32<<<(n4x+255)/256, 256>>>((const float4*)x, (float4*)g_xr_p, n4x);
    round_tf32<<<(n4q+255)/256, 256>>>((const float4*)w_qkv, (float4*)g_wq_p, n4q);
    round_tf32<<<(n4p+255)/256, 256>>>((const float4*)w_proj, (float4*)g_wp_p, n4p);

    qkv_gemm<<<dim3(NQKV/128, M_/128), 256, GEMM_SMEM>>>();
    attn_kernel<<<dim3(T_/64, B_*H_), 256, ATTN_SMEM>>>();
    proj_gemm<<<dim3(C_/128, M_/128), 256, GEMM_SMEM>>>(b_proj, out);
}

// round 7
// speedup vs baseline: 3.0535x; 1.0783x over previous
#include <cuda_runtime.h>
#include <math.h>

#define B_ 2
#define T_ 2048
#define C_ 1024
#define H_ 16
#define D_ 64
#define M_ (B_*T_)          // 4096
#define NQKV (3*C_)         // 3072

typedef unsigned int u32;

// Scratch (allocation-free rule: __device__ globals)
__device__ float g_q[(size_t)B_*H_*T_*D_];     // tf32-grid values
__device__ float g_k[(size_t)B_*H_*T_*D_];     // tf32-grid values
__device__ float g_v[(size_t)B_*H_*T_*D_];     // tf32-grid values
__device__ float g_att[(size_t)M_*C_];         // [b][t][h][d], tf32-grid
__device__ float g_xr[(size_t)M_*C_];          // tf32-rounded x
__device__ float g_wq[(size_t)C_*NQKV];        // tf32-rounded w_qkv
__device__ float g_wp[(size_t)C_*C_];          // tf32-rounded w_proj

__device__ __forceinline__ u32 f2tf(float x) {
    u32 r; asm("cvt.rna.tf32.f32 %0, %1;" : "=r"(r) : "f"(x)); return r;
}
__device__ __forceinline__ float f2tff(float x) { return __uint_as_float(f2tf(x)); }

__device__ __forceinline__ void mma_tf32(float c[4], u32 a0, u32 a1, u32 a2, u32 a3,
                                         u32 b0, u32 b1) {
    asm volatile("mma.sync.aligned.m16n8k8.row.col.f32.tf32.tf32.f32 "
                 "{%0,%1,%2,%3}, {%4,%5,%6,%7}, {%8,%9}, {%0,%1,%2,%3};"
                 : "+f"(c[0]), "+f"(c[1]), "+f"(c[2]), "+f"(c[3])
                 : "r"(a0), "r"(a1), "r"(a2), "r"(a3), "r"(b0), "r"(b1));
}
__device__ __forceinline__ void cp16(u32* smem, const void* gmem) {
    u32 s = (u32)__cvta_generic_to_shared(smem);
    asm volatile("cp.async.cg.shared.global [%0], [%1], 16;\n" :: "r"(s), "l"(gmem));
}

// ---------------------------------------------------------------------------
// Prep: round arrays to the tf32 grid.
// ---------------------------------------------------------------------------
__global__ void round_tf32(const float4* __restrict__ s, float4* __restrict__ d, int n4) {
    int i = blockIdx.x * blockDim.x + threadIdx.x;
    if (i < n4) {
        float4 v = s[i];
        float4 r;
        r.x = f2tff(v.x); r.y = f2tff(v.y); r.z = f2tff(v.z); r.w = f2tff(v.w);
        d[i] = r;
    }
}

// ---------------------------------------------------------------------------
// tf32 tensor-core GEMM: 128x128 tile, BK=32, 256 threads (8 warps 2m x 4n),
// cp.async 2-stage double-buffered smem. 2 CTAs/SM via launch bounds.
// ---------------------------------------------------------------------------
#define AS_STRIDE 36
#define BS_STRIDE 132
#define NIT (C_/32)

struct GemmFrags { float c[4][4][4]; };   // [mt][nt][frag]

template<int NDIM>
__device__ __forceinline__ void gemm_cp_body(const float* __restrict__ A,
                                             const float* __restrict__ Bw,
                                             u32* As, u32* Bs,
                                             int m0, int n0, GemmFrags& F) {
    int tid = threadIdx.x;
    int lane = tid & 31, wid = tid >> 5;
    int warp_m = wid >> 2, warp_n = wid & 3;    // 2 x 4
    int lr = lane >> 2, lc = lane & 3;

    auto issue = [&](int k0, int b) {
        u32* Ab = As + b * 128 * AS_STRIDE;
        u32* Bb = Bs + b * 32 * BS_STRIDE;
        #pragma unroll
        for (int it = 0; it < 4; ++it) {
            int id = it*256 + tid;
            int row = id >> 3, c = (id & 7) * 4;
            cp16(Ab + row*AS_STRIDE + c, A + (size_t)(m0 + row)*C_ + k0 + c);
        }
        #pragma unroll
        for (int it = 0; it < 4; ++it) {
            int id = it*256 + tid;
            int krow = id >> 5, c = (id & 31) * 4;
            cp16(Bb + krow*BS_STRIDE + c, Bw + (size_t)(k0 + krow)*NDIM + n0 + c);
        }
        asm volatile("cp.async.commit_group;\n");
    };

    issue(0, 0);
    for (int it = 0; it < NIT; ++it) {
        if (it + 1 < NIT) {
            issue((it+1)*32, (it+1) & 1);
            asm volatile("cp.async.wait_group 1;\n");
        } else {
            asm volatile("cp.async.wait_group 0;\n");
        }
        __syncthreads();
        u32* Ab = As + (it & 1) * 128 * AS_STRIDE;
        u32* Bb = Bs + (it & 1) * 32 * BS_STRIDE;
        #pragma unroll
        for (int kc = 0; kc < 4; ++kc) {
            int kk = kc * 8;
            u32 af[4][4], bf[4][2];
            #pragma unroll
            for (int mt = 0; mt < 4; ++mt) {
                int mr = warp_m*64 + mt*16;
                af[mt][0] = Ab[(mr + lr    )*AS_STRIDE + kk + lc    ];
                af[mt][1] = Ab[(mr + lr + 8)*AS_STRIDE + kk + lc    ];
                af[mt][2] = Ab[(mr + lr    )*AS_STRIDE + kk + lc + 4];
                af[mt][3] = Ab[(mr + lr + 8)*AS_STRIDE + kk + lc + 4];
            }
            #pragma unroll
            for (int nt = 0; nt < 4; ++nt) {
                int nc = warp_n*32 + nt*8;
                bf[nt][0] = Bb[(kk + lc    )*BS_STRIDE + nc + lr];
                bf[nt][1] = Bb[(kk + lc + 4)*BS_STRIDE + nc + lr];
            }
            #pragma unroll
            for (int mt = 0; mt < 4; ++mt)
                #pragma unroll
                for (int nt = 0; nt < 4; ++nt)
                    mma_tf32(F.c[mt][nt], af[mt][0], af[mt][1], af[mt][2], af[mt][3],
                             bf[nt][0], bf[nt][1]);
        }
        __syncthreads();
    }
}

#define GEMM_SMEM ((2*(128*AS_STRIDE + 32*BS_STRIDE)) * 4)   // 70656 B

__global__ __launch_bounds__(256, 2) void qkv_gemm() {
    extern __shared__ u32 smg[];
    u32* As = smg;
    u32* Bs = smg + 2*128*AS_STRIDE;
    int tid = threadIdx.x;
    int lane = tid & 31, wid = tid >> 5;
    int warp_m = wid >> 2, warp_n = wid & 3;
    int lr = lane >> 2, lc = lane & 3;
    int m0 = blockIdx.y * 128, n0 = blockIdx.x * 128;

    GemmFrags F = {};
    gemm_cp_body<NQKV>(g_xr, g_wq, As, Bs, m0, n0, F);

    // Epilogue: scatter qkv, rounding to tf32 grid so attn can cp.async raw bytes.
    #pragma unroll
    for (int mt = 0; mt < 4; ++mt) {
        #pragma unroll
        for (int nt = 0; nt < 4; ++nt) {
            #pragma unroll
            for (int f = 0; f < 4; ++f) {
                int m = m0 + warp_m*64 + mt*16 + lr + (f >> 1)*8;
                int n = n0 + warp_n*32 + nt*8 + lc*2 + (f & 1);
                int bb = m >> 11, t = m & 2047;
                int three = n % 3;
                int hd = n / 3;
                int h = hd >> 6, d = hd & 63;
                size_t dst = (((size_t)(bb*H_ + h))*T_ + t)*D_ + d;
                float v = f2tff(F.c[mt][nt][f]);
                if (three == 0)      g_q[dst] = v;
                else if (three == 1) g_k[dst] = v;
                else                 g_v[dst] = v;
            }
        }
    }
}

__global__ __launch_bounds__(256, 2) void proj_gemm(const float* __restrict__ bias,
                                                    float* __restrict__ out) {
    extern __shared__ u32 smg[];
    u32* As = smg;
    u32* Bs = smg + 2*128*AS_STRIDE;
    int tid = threadIdx.x;
    int lane = tid & 31, wid = tid >> 5;
    int warp_m = wid >> 2, warp_n = wid & 3;
    int lr = lane >> 2, lc = lane & 3;
    int m0 = blockIdx.y * 128, n0 = blockIdx.x * 128;

    GemmFrags F = {};
    gemm_cp_body<C_>(g_att, g_wp, As, Bs, m0, n0, F);

    #pragma unroll
    for (int mt = 0; mt < 4; ++mt) {
        #pragma unroll
        for (int nt = 0; nt < 4; ++nt) {
            #pragma unroll
            for (int f = 0; f < 4; ++f) {
                int m = m0 + warp_m*64 + mt*16 + lr + (f >> 1)*8;
                int n = n0 + warp_n*32 + nt*8 + lc*2 + (f & 1);
                out[(size_t)m * C_ + n] = F.c[mt][nt][f] + bias[n];
            }
        }
    }
}

// ---------------------------------------------------------------------------
// Flash attention, tf32 mma phases, cp.async double-buffered K/V tiles.
// BQ=64, BK=64, 256 threads = 8 warps as 4(m) x 2(n).
// Q/K stride 68 (==4 mod 32), V stride 72 (==8 mod 32): conflict-free frags.
// Inputs are already tf32-grid (qkv epilogue rounds), so raw byte copies are
// exact under mma truncation.
// ---------------------------------------------------------------------------
#define QS 68
#define VSS 72
// word offsets
#define OFF_K  (64*QS)                 // Ks[2][64][QS]
#define OFF_V  (OFF_K + 2*64*QS)       // Vs[2][64][VSS]
#define OFF_S  (OFF_V + 2*64*VSS)      // Ss[64][QS]
#define OFF_M  (OFF_S + 64*QS)
#define ATTN_SMEM ((OFF_M + 3*64) * 4) // bytes

__global__ __launch_bounds__(256, 2) void attn_kernel() {
    extern __shared__ char smc[];
    u32* Qs = (u32*)smc;
    u32* Kb = Qs + OFF_K;
    u32* Vb = Qs + OFF_V;
    float* Ss = (float*)(Qs + OFF_S);
    u32* Ps = (u32*)Ss;
    float* mrow = (float*)(Qs + OFF_M);
    float* lrow = mrow + 64;
    float* rrow = lrow + 64;

    int tid = threadIdx.x;
    int lane = tid & 31, wid = tid >> 5;
    int warp_m = wid >> 1, warp_n = wid & 1;
    int lr = lane >> 2, lc = lane & 3;
    int mr = warp_m * 16;

    int bh = blockIdx.y;
    int b = bh >> 4, h = bh & 15;
    int qBase = blockIdx.x * 64;

    const float* qg  = g_q + (((size_t)(b*H_ + h))*T_ + qBase)*D_;
    const float* kgb = g_k + ((size_t)(b*H_ + h))*T_*D_;
    const float* vgb = g_v + ((size_t)(b*H_ + h))*T_*D_;

    auto issueKV = [&](int kt, int s) {
        const float* kg = kgb + (size_t)kt*64*D_;
        const float* vg = vgb + (size_t)kt*64*D_;
        u32* Kd = Kb + s*64*QS;
        u32* Vd = Vb + s*64*VSS;
        #pragma unroll
        for (int it = 0; it < 4; ++it) {
            int id = it*256 + tid;
            int row = id >> 4, c = (id & 15) * 4;
            cp16(Kd + row*QS + c, kg + (size_t)row*D_ + c);
            cp16(Vd + row*VSS + c, vg + (size_t)row*D_ + c);
        }
        asm volatile("cp.async.commit_group;\n");
    };

    // group 0: Q + K0 + V0
    #pragma unroll
    for (int it = 0; it < 4; ++it) {
        int id = it*256 + tid;
        int row = id >> 4, c = (id & 15) * 4;
        cp16(Qs + row*QS + c, qg + (size_t)row*D_ + c);
    }
    issueKV(0, 0);
    if (tid < 64) { mrow[tid] = -INFINITY; lrow[tid] = 0.0f; }

    float o[4][4] = {};
    const float scale = 0.125f;
    int nkt = blockIdx.x + 1;

    for (int kt = 0; kt < nkt; ++kt) {
        int s = kt & 1;
        if (kt + 1 < nkt) {
            issueKV(kt+1, s^1);
            asm volatile("cp.async.wait_group 1;\n");
        } else {
            asm volatile("cp.async.wait_group 0;\n");
        }
        __syncthreads();
        u32* Ks = Kb + s*64*QS;
        u32* Vs = Vb + s*64*VSS;
        int kBase = kt * 64;

        // Phase A: S = Q K^T
        {
            float sacc[4][4] = {};
            #pragma unroll
            for (int kk = 0; kk < 64; kk += 8) {
                u32 a0 = Qs[(mr+lr  )*QS + kk+lc  ];
                u32 a1 = Qs[(mr+lr+8)*QS + kk+lc  ];
                u32 a2 = Qs[(mr+lr  )*QS + kk+lc+4];
                u32 a3 = Qs[(mr+lr+8)*QS + kk+lc+4];
                #pragma unroll
                for (int nt = 0; nt < 4; ++nt) {
                    int nc = warp_n*32 + nt*8;
                    u32 b0 = Ks[(nc+lr)*QS + kk+lc  ];
                    u32 b1 = Ks[(nc+lr)*QS + kk+lc+4];
                    mma_tf32(sacc[nt], a0, a1, a2, a3, b0, b1);
                }
            }
            #pragma unroll
            for (int nt = 0; nt < 4; ++nt) {
                int nc = warp_n*32 + nt*8;
                #pragma unroll
                for (int f = 0; f < 4; ++f) {
                    int row = mr + lr + (f >> 1)*8;
                    int col = nc + lc*2 + (f & 1);
                    int qi = qBase + row, kj = kBase + col;
                    Ss[row*QS + col] = (kj <= qi) ? sacc[nt][f]*scale : -INFINITY;
                }
            }
        }
        __syncthreads();

        // Phase B: online softmax; P (tf32) overwrites S in place
        {
            int row = tid >> 2, g = tid & 3;
            float sv[16];
            float lm = -INFINITY;
            #pragma unroll
            for (int j = 0; j < 16; ++j) {
                sv[j] = Ss[row*QS + g*16 + j];
                lm = fmaxf(lm, sv[j]);
            }
            lm = fmaxf(lm, __shfl_xor_sync(0xffffffffu, lm, 1));
            lm = fmaxf(lm, __shfl_xor_sync(0xffffffffu, lm, 2));
            float newm = fmaxf(mrow[row], lm);
            float ls = 0.0f;
            #pragma unroll
            for (int j = 0; j < 16; ++j) {
                float p = __expf(sv[j] - newm);
                ls += p;
                Ps[row*QS + g*16 + j] = f2tf(p);
            }
            ls += __shfl_xor_sync(0xffffffffu, ls, 1);
            ls += __shfl_xor_sync(0xffffffffu, ls, 2);
            if (g == 0) {
                float r = __expf(mrow[row] - newm);
                rrow[row] = r;
                lrow[row] = lrow[row] * r + ls;
                mrow[row] = newm;
            }
        }
        __syncthreads();

        // Phase C: O = O*r + P V
        {
            float r0 = rrow[mr + lr], r1 = rrow[mr + lr + 8];
            #pragma unroll
            for (int nt = 0; nt < 4; ++nt) {
                o[nt][0] *= r0; o[nt][1] *= r0;
                o[nt][2] *= r1; o[nt][3] *= r1;
            }
            #pragma unroll
            for (int kk = 0; kk < 64; kk += 8) {
                u32 a0 = Ps[(mr+lr  )*QS + kk+lc  ];
                u32 a1 = Ps[(mr+lr+8)*QS + kk+lc  ];
                u32 a2 = Ps[(mr+lr  )*QS + kk+lc+4];
                u32 a3 = Ps[(mr+lr+8)*QS + kk+lc+4];
                #pragma unroll
                for (int nt = 0; nt < 4; ++nt) {
                    int nc = warp_n*32 + nt*8;
                    u32 b0 = Vs[(kk+lc  )*VSS + nc+lr];
                    u32 b1 = Vs[(kk+lc+4)*VSS + nc+lr];
                    mma_tf32(o[nt], a0, a1, a2, a3, b0, b1);
                }
            }
        }
        __syncthreads();   // protect K/V buffer before next iteration's issue
    }

    // Epilogue: normalize, round to tf32 grid, write [b][t][h][d]
    #pragma unroll
    for (int half = 0; half < 2; ++half) {
        int row = mr + lr + half*8;
        float inv = 1.0f / lrow[row];
        int t = qBase + row;
        float* og = g_att + (((size_t)(b*T_ + t))*H_ + h)*D_;
        #pragma unroll
        for (int nt = 0; nt < 4; ++nt) {
            int d = warp_n*32 + nt*8 + lc*2;
            float2 w;
            w.x = f2tff(o[nt][half*2+0] * inv);
            w.y = f2tff(o[nt][half*2+1] * inv);
            *(float2*)(og + d) = w;
        }
    }
}

// ---------------------------------------------------------------------------
extern "C" void kernel_launch(void* const* d_in, const int* in_sizes, int n_in,
                              void* d_out, int out_size) {
    const float* x      = (const float*)d_in[0];
    const float* w_qkv  = (const float*)d_in[1];
    const float* w_proj = (const float*)d_in[2];
    const float* b_proj = (const float*)d_in[3];
    float* out = (float*)d_out;

    cudaFuncSetAttribute(attn_kernel,
                         cudaFuncAttributeMaxDynamicSharedMemorySize, ATTN_SMEM);
    cudaFuncSetAttribute(qkv_gemm,
                         cudaFuncAttributeMaxDynamicSharedMemorySize, GEMM_SMEM);
    cudaFuncSetAttribute(proj_gemm,
                         cudaFuncAttributeMaxDynamicSharedMemorySize, GEMM_SMEM);

    float *g_xr_p, *g_wq_p, *g_wp_p;
    cudaGetSymbolAddress((void**)&g_xr_p, g_xr);
    cudaGetSymbolAddress((void**)&g_wq_p, g_wq);
    cudaGetSymbolAddress((void**)&g_wp_p, g_wp);

    int n4x = M_*C_/4, n4q = C_*NQKV/4, n4p = C_*C_/4;
    round_tf32<<<(n4x+255)/256, 256>>>((const float4*)x, (float4*)g_xr_p, n4x);
    round_tf32<<<(n4q+255)/256, 256>>>((const float4*)w_qkv, (float4*)g_wq_p, n4q);
    round_tf32<<<(n4p+255)/256, 256>>>((const float4*)w_proj, (float4*)g_wp_p, n4p);

    qkv_gemm<<<dim3(NQKV/128, M_/128), 256, GEMM_SMEM>>>();
    attn_kernel<<<dim3(T_/64, B_*H_), 256, ATTN_SMEM>>>();
    proj_gemm<<<dim3(C_/128, M_/128), 256, GEMM_SMEM>>>(b_proj, out);
}